// round 1
// baseline (speedup 1.0000x reference)
#include <cuda_runtime.h>

// Half-lattice hop operator:
//   out = DIAG*psi - 0.5 * sum_mu ( K_fwd[mu] @ psi(fwd nbr) + K_bwd[mu] @ psi(bwd nbr) )
// Lattice T=Z=Y=16, X/2=8, D=12 complex components per site.
// mu=0..2: periodic shift along T/Z/Y. mu=3: staggered X hop gated by parity
// r=(t+z+y)%2 (fwd iff r==1, bwd iff r==0, else identity).

#define LT 16
#define LZ 16
#define LY 16
#define LX 8
#define DD 12
#define NV (LT*LZ*LY*LX)   // 32768 sites
#define DIAGC 4.5f

__device__ __forceinline__ void cmatvec_row(
    const float* __restrict__ Kr, const float* __restrict__ Ki,
    const float* __restrict__ pr, const float* __restrict__ pi,
    float& hr, float& hi)
{
    const float4* kr4 = reinterpret_cast<const float4*>(Kr);
    const float4* ki4 = reinterpret_cast<const float4*>(Ki);
    const float4* pr4 = reinterpret_cast<const float4*>(pr);
    const float4* pi4 = reinterpret_cast<const float4*>(pi);
#pragma unroll
    for (int c = 0; c < 3; ++c) {
        float4 kr = __ldg(kr4 + c);
        float4 ki = __ldg(ki4 + c);
        float4 vr = __ldg(pr4 + c);
        float4 vi = __ldg(pi4 + c);
        hr = fmaf(kr.x, vr.x, hr); hr = fmaf(-ki.x, vi.x, hr);
        hi = fmaf(kr.x, vi.x, hi); hi = fmaf( ki.x, vr.x, hi);
        hr = fmaf(kr.y, vr.y, hr); hr = fmaf(-ki.y, vi.y, hr);
        hi = fmaf(kr.y, vi.y, hi); hi = fmaf( ki.y, vr.y, hi);
        hr = fmaf(kr.z, vr.z, hr); hr = fmaf(-ki.z, vi.z, hr);
        hi = fmaf(kr.z, vi.z, hi); hi = fmaf( ki.z, vr.z, hi);
        hr = fmaf(kr.w, vr.w, hr); hr = fmaf(-ki.w, vi.w, hr);
        hi = fmaf(kr.w, vi.w, hi); hi = fmaf( ki.w, vr.w, hi);
    }
}

__global__ __launch_bounds__(192)
void hop_kernel(const float* __restrict__ psr, const float* __restrict__ psi,
                const float* __restrict__ Kfr, const float* __restrict__ Kfi,
                const float* __restrict__ Kbr, const float* __restrict__ Kbi,
                float* __restrict__ out)
{
    const int site = blockIdx.x * blockDim.y + threadIdx.y;
    const int i = threadIdx.x;   // 0..11, output component (matrix row)
    if (site >= NV) return;

    // site bits: x [0:3), y [3:7), z [7:11), t [11:15)
    const int x = site & 7;
    const int y = (site >> 3) & 15;
    const int z = (site >> 7) & 15;
    const int t = (site >> 11) & 15;

    const int nTf = (site & ~(15 << 11)) | (((t + 1) & 15) << 11);
    const int nTb = (site & ~(15 << 11)) | (((t + 15) & 15) << 11);
    const int nZf = (site & ~(15 << 7))  | (((z + 1) & 15) << 7);
    const int nZb = (site & ~(15 << 7))  | (((z + 15) & 15) << 7);
    const int nYf = (site & ~(15 << 3))  | (((y + 1) & 15) << 3);
    const int nYb = (site & ~(15 << 3))  | (((y + 15) & 15) << 3);
    const int r = (t + z + y) & 1;
    const int nXf = r ? ((site & ~7) | ((x + 1) & 7)) : site;   // fwd hop iff r==1
    const int nXb = (!r) ? ((site & ~7) | ((x + 7) & 7)) : site; // bwd hop iff r==0

    const int nf[4] = {nTf, nZf, nYf, nXf};
    const int nb[4] = {nTb, nZb, nYb, nXb};

    float hr = 0.0f, hi = 0.0f;
    const size_t rowoff = (size_t)site * (DD * DD) + (size_t)i * DD;

#pragma unroll
    for (int mu = 0; mu < 4; ++mu) {
        const size_t ko = (size_t)mu * ((size_t)NV * DD * DD) + rowoff;
        cmatvec_row(Kfr + ko, Kfi + ko,
                    psr + (size_t)nf[mu] * DD, psi + (size_t)nf[mu] * DD,
                    hr, hi);
        cmatvec_row(Kbr + ko, Kbi + ko,
                    psr + (size_t)nb[mu] * DD, psi + (size_t)nb[mu] * DD,
                    hr, hi);
    }

    const size_t so = (size_t)site * DD + i;
    const float pre = __ldg(psr + so);
    const float pim = __ldg(psi + so);
    out[so]                      = DIAGC * pre - 0.5f * hr;
    out[(size_t)NV * DD + so]    = DIAGC * pim - 0.5f * hi;
}

extern "C" void kernel_launch(void* const* d_in, const int* in_sizes, int n_in,
                              void* d_out, int out_size)
{
    const float* psr = (const float*)d_in[0];
    const float* psi = (const float*)d_in[1];
    const float* Kfr = (const float*)d_in[2];
    const float* Kfi = (const float*)d_in[3];
    const float* Kbr = (const float*)d_in[4];
    const float* Kbi = (const float*)d_in[5];
    float* out = (float*)d_out;

    // 12 threads (rows) x 16 sites per block = 192 threads; 2048 blocks.
    dim3 block(12, 16);
    dim3 grid(NV / 16);
    hop_kernel<<<grid, block>>>(psr, psi, Kfr, Kfi, Kbr, Kbi, out);
}